// round 12
// baseline (speedup 1.0000x reference)
#include <cuda_runtime.h>

#define BB   8
#define NN   4096
#define DIN  128
#define DOUT 256
#define SS   1024
#define KKNN 16
#define MTOT (BB*SS*KKNN)
#define XYZ_OFF (BB*SS*DOUT)

__device__ float  g_h[BB*NN*DOUT];      // h for all points (33.5MB, L2-resident)
__device__ float  g_hmax[BB*SS*DOUT];   // per-sample max over K (8MB)
__device__ int    g_knn[MTOT];
__device__ double g_sum[DOUT];
__device__ double g_sumsq[DOUT];

// ---- f32x2 packed helpers: per-element round-to-nearest == scalar RN ----
__device__ __forceinline__ unsigned long long pk2(float lo, float hi) {
    unsigned long long r;
    asm("mov.b64 %0, {%1, %2};" : "=l"(r) : "f"(lo), "f"(hi));
    return r;
}
__device__ __forceinline__ void upk2(unsigned long long v, float& lo, float& hi) {
    asm("mov.b64 {%0, %1}, %2;" : "=f"(lo), "=f"(hi) : "l"(v));
}
__device__ __forceinline__ unsigned long long add2(unsigned long long a, unsigned long long b) {
    unsigned long long r;
    asm("add.rn.f32x2 %0, %1, %2;" : "=l"(r) : "l"(a), "l"(b));
    return r;
}
__device__ __forceinline__ unsigned long long mul2(unsigned long long a, unsigned long long b) {
    unsigned long long r;
    asm("mul.rn.f32x2 %0, %1, %2;" : "=l"(r) : "l"(a), "l"(b));
    return r;
}

// no-op launches: shift the ncu -s 5 -c 1 capture window onto k1
__global__ void k0_nop() {}

// ---------------------------------------------------------------------------
// K1: blocks 0..7 = FPS (one batch each); blocks 8.. = exact-fp32 SGEMM.
// FPS iteration: packed f32x2 distance (bit-frozen), bit-compare min/argmax,
// warp REDUX pair, then ONE SMEM atomicMax on a (iter_tag|dist|rev-idx) key —
// single barrier, single LDS.64 after it. Sample coords written in bulk after
// the loop.
// ---------------------------------------------------------------------------
__global__ __launch_bounds__(1024) void k1_fps_gemm(
    const float* __restrict__ feat, const float* __restrict__ xyz,
    const float* __restrict__ W, const float* __restrict__ bias,
    float* __restrict__ out)
{
    extern __shared__ float sm[];
    const int tid = threadIdx.x;
    const int bid = blockIdx.x;

    if (bid < BB) {
        float* sx = sm;  float* sy = sm + NN;  float* sz = sm + 2*NN;
        unsigned long long* np  = (unsigned long long*)(sm + 3*NN);
        unsigned long long* npx = np;          // packed {-x,-x} per point
        unsigned long long* npy = np + NN;
        unsigned long long* npz = np + 2*NN;
        unsigned* widx = (unsigned*)(np + 3*NN);              // [SS]
        unsigned long long* slot = (unsigned long long*)(widx + SS);

        const float* bx = xyz + (size_t)bid * NN * 3;
        float px[4], py[4], pz[4];
        #pragma unroll
        for (int j = 0; j < 4; j++) {
            int i = j*1024 + tid;
            float x = bx[i*3+0], y = bx[i*3+1], z = bx[i*3+2];
            px[j]=x; py[j]=y; pz[j]=z;
            sx[i]=x; sy[i]=y; sz[i]=z;
            float nx = __uint_as_float(__float_as_uint(x) ^ 0x80000000u);
            float ny = __uint_as_float(__float_as_uint(y) ^ 0x80000000u);
            float nz = __uint_as_float(__float_as_uint(z) ^ 0x80000000u);
            npx[i] = pk2(nx, nx);
            npy[i] = pk2(ny, ny);
            npz[i] = pk2(nz, nz);
        }
        const unsigned long long pX01 = pk2(px[0], px[1]), pX23 = pk2(px[2], px[3]);
        const unsigned long long pY01 = pk2(py[0], py[1]), pY23 = pk2(py[2], py[3]);
        const unsigned long long pZ01 = pk2(pz[0], pz[1]), pZ23 = pk2(pz[2], pz[3]);
        const unsigned INIT = __float_as_uint(1e10f);
        unsigned du0=INIT, du1=INIT, du2=INIT, du3=INIT;
        if (tid == 0) { *slot = 0ULL; widx[0] = 0u; }
        __syncthreads();

        unsigned w = 0;
        const unsigned rb = 4095u - (unsigned)tid;    // reversed index base
        const int lane = tid & 31;

        for (int s = 1; s < SS; s++) {
            unsigned long long Lx = npx[w], Ly = npy[w], Lz = npz[w];
            // d = (dx*dx + dy*dy) + dz*dz, dx = p + (-l)  (exact, bit-frozen)
            unsigned long long dxA = add2(pX01, Lx), dyA = add2(pY01, Ly), dzA = add2(pZ01, Lz);
            unsigned long long sA  = add2(add2(mul2(dxA,dxA), mul2(dyA,dyA)), mul2(dzA,dzA));
            unsigned long long dxB = add2(pX23, Lx), dyB = add2(pY23, Ly), dzB = add2(pZ23, Lz);
            unsigned long long sB  = add2(add2(mul2(dxB,dxB), mul2(dyB,dyB)), mul2(dzB,dzB));
            float d0,d1,d2,d3;
            upk2(sA, d0, d1);  upk2(sB, d2, d3);
            du0 = min(du0, __float_as_uint(d0));
            du1 = min(du1, __float_as_uint(d1));
            du2 = min(du2, __float_as_uint(d2));
            du3 = min(du3, __float_as_uint(d3));
            // thread best: max value; ties -> smaller idx == larger reversed idx
            unsigned b01 = max(du0, du1);  unsigned r01 = (du0 >= du1) ? rb          : (rb - 1024u);
            unsigned b23 = max(du2, du3);  unsigned r23 = (du2 >= du3) ? (rb - 2048u) : (rb - 3072u);
            unsigned bv  = max(b01, b23);  unsigned rr  = (b01 >= b23) ? r01 : r23;
            // warp argmax: max value, then max reversed-idx among maxers
            unsigned m    = __reduce_max_sync(0xffffffffu, bv);
            unsigned rwin = __reduce_max_sync(0xffffffffu, (bv == m) ? rr : 0u);
            if (lane == 0) {
                unsigned long long pk = ((unsigned long long)s << 44)
                                      | ((unsigned long long)m << 12)
                                      | (unsigned long long)rwin;
                atomicMax(slot, pk);   // iteration tag makes stale values lose
            }
            __syncthreads();
            unsigned long long win = *slot;
            w = 4095u - (unsigned)(win & 0xFFFULL);
            if (tid == 0) widx[s] = w;
        }
        __syncthreads();
        // bulk write sample_xyz
        for (int i = tid; i < SS; i += 1024) {
            unsigned ww = widx[i];
            float* o = out + XYZ_OFF + (size_t)(bid*SS + i)*3;
            o[0] = sx[ww]; o[1] = sy[ww]; o[2] = sz[ww];
        }
    } else {
        // -------- SGEMM: h = feat @ W^T + b, exact fp32 --------
        const int g = bid - BB;
        const int rowBase = (g & 255) * 128;
        const int colBase = (g >> 8) * 128;
        float* As = sm;              // [16][132]
        float* Bs = sm + 16*132;     // [16][132]
        const int l = tid & 31, w = tid >> 5;
        const int tm = l*4, tn = w*4;
        float acc[4][4];
        #pragma unroll
        for (int i=0;i<4;i++)
            #pragma unroll
            for (int j=0;j<4;j++) acc[i][j] = 0.f;

        for (int kc = 0; kc < DIN; kc += 16) {
            if (tid < 512) {
                int r = tid >> 2, q = tid & 3;
                float4 v = *(const float4*)(feat + (size_t)(rowBase + r)*DIN + kc + q*4);
                As[(q*4+0)*132 + r] = v.x;
                As[(q*4+1)*132 + r] = v.y;
                As[(q*4+2)*132 + r] = v.z;
                As[(q*4+3)*132 + r] = v.w;
            } else {
                int t2 = tid - 512; int c = t2 >> 2, q = t2 & 3;
                float4 v = *(const float4*)(W + (size_t)(colBase + c)*DIN + kc + q*4);
                Bs[(q*4+0)*132 + c] = v.x;
                Bs[(q*4+1)*132 + c] = v.y;
                Bs[(q*4+2)*132 + c] = v.z;
                Bs[(q*4+3)*132 + c] = v.w;
            }
            __syncthreads();
            #pragma unroll
            for (int kk = 0; kk < 16; kk++) {
                float4 a  = *(const float4*)(As + kk*132 + tm);
                float4 bb = *(const float4*)(Bs + kk*132 + tn);
                acc[0][0] += a.x*bb.x; acc[0][1] += a.x*bb.y; acc[0][2] += a.x*bb.z; acc[0][3] += a.x*bb.w;
                acc[1][0] += a.y*bb.x; acc[1][1] += a.y*bb.y; acc[1][2] += a.y*bb.z; acc[1][3] += a.y*bb.w;
                acc[2][0] += a.z*bb.x; acc[2][1] += a.z*bb.y; acc[2][2] += a.z*bb.z; acc[2][3] += a.z*bb.w;
                acc[3][0] += a.w*bb.x; acc[3][1] += a.w*bb.y; acc[3][2] += a.w*bb.z; acc[3][3] += a.w*bb.w;
            }
            __syncthreads();
        }
        #pragma unroll
        for (int i = 0; i < 4; i++) {
            int row = rowBase + tm + i;
            float4 o;
            o.x = acc[i][0] + bias[colBase+tn+0];
            o.y = acc[i][1] + bias[colBase+tn+1];
            o.z = acc[i][2] + bias[colBase+tn+2];
            o.w = acc[i][3] + bias[colBase+tn+3];
            *(float4*)(g_h + (size_t)row*DOUT + colBase + tn) = o;
        }
    }
}

// ---------------------------------------------------------------------------
// K2: KNN — fp32 expansion prefilter, fp64 difference-form re-rank (exact).
// ---------------------------------------------------------------------------
__global__ __launch_bounds__(256) void k2_knn(
    const float* __restrict__ xyz, const float* __restrict__ out)
{
    extern __shared__ float sm[];
    float* sx = sm;  float* sy = sm + NN;  float* sz = sm + 2*NN;  float* p2 = sm + 3*NN;
    float* md = sm + 4*NN;               // [256][16]
    int*   mi = (int*)(md + 256*16);     // [256][16]
    const int tid = threadIdx.x;
    const int b = blockIdx.x >> 3;
    const int chunk = blockIdx.x & 7;

    if (blockIdx.x == 0) { g_sum[tid] = 0.0; g_sumsq[tid] = 0.0; }

    const float* bx = xyz + (size_t)b * NN * 3;
    for (int i = tid; i < NN; i += 256) {
        float x = bx[i*3], y = bx[i*3+1], z = bx[i*3+2];
        sx[i]=x; sy[i]=y; sz[i]=z;
        p2[i] = __fmaf_rn(z, z, __fmaf_rn(y, y, __fmul_rn(x, x)));
    }
    __syncthreads();

    const int q = chunk*128 + (tid & 127);
    const int half = tid >> 7;
    const float* qp = out + XYZ_OFF + (size_t)(b*SS + q)*3;
    const float qx = qp[0], qy = qp[1], qz = qp[2];
    const float q2 = __fmaf_rn(qz, qz, __fmaf_rn(qy, qy, __fmul_rn(qx, qx)));

    float dk[16]; int ik[16];
    #pragma unroll
    for (int j = 0; j < 16; j++) { dk[j] = 3.4e38f; ik[j] = 0; }

    const int i0 = half * 2048;
    #pragma unroll 2
    for (int i = i0; i < i0 + 2048; i++) {
        float dot = __fmaf_rn(qz, sz[i], __fmaf_rn(qy, sy[i], __fmul_rn(qx, sx[i])));
        float d   = __fmaf_rn(-2.0f, dot, __fadd_rn(q2, p2[i]));
        if (d < dk[15]) {
            dk[15] = d; ik[15] = i;
            #pragma unroll
            for (int j = 15; j > 0; --j) {
                if (dk[j] < dk[j-1]) {
                    float td = dk[j]; dk[j] = dk[j-1]; dk[j-1] = td;
                    int   ti = ik[j]; ik[j] = ik[j-1]; ik[j-1] = ti;
                } else break;
            }
        }
    }
    #pragma unroll
    for (int j = 0; j < 16; j++) { md[tid*16+j] = dk[j]; mi[tid*16+j] = ik[j]; }
    __syncthreads();

    if (tid < 128) {
        int cand[32];
        #pragma unroll
        for (int j = 0; j < 16; j++) {
            cand[j]    = mi[tid*16 + j];
            cand[16+j] = mi[(tid+128)*16 + j];
        }
        const double qdx = (double)qx, qdy = (double)qy, qdz = (double)qz;
        double dd[32];
        #pragma unroll
        for (int j = 0; j < 32; j++) {
            int c = cand[j];
            double ax = (double)sx[c] - qdx;
            double ay = (double)sy[c] - qdy;
            double az = (double)sz[c] - qdz;
            dd[j] = ax*ax + ay*ay + az*az;
        }
        int* dst = g_knn + (size_t)(b*SS + q)*KKNN;
        for (int s = 0; s < 16; s++) {
            int best = s;
            for (int j = s+1; j < 32; j++) {
                if (dd[j] < dd[best] ||
                    (dd[j] == dd[best] && cand[j] < cand[best])) best = j;
            }
            double td = dd[best]; dd[best] = dd[s]; dd[s] = td;
            int    tc = cand[best]; cand[best] = cand[s]; cand[s] = tc;
            dst[s] = tc;
        }
    }
}

// ---------------------------------------------------------------------------
// K3: fused BN statistics (fp64 acc) + per-sample max over K (single gather).
// ---------------------------------------------------------------------------
__global__ __launch_bounds__(256) void k3_stats()
{
    __shared__ int sbase[512];
    const int tid = threadIdx.x;
    const int r0 = blockIdx.x * 512;
    for (int j = tid; j < 512; j += 256) {
        int r = r0 + j;
        int b = r >> 14;
        sbase[j] = (b*NN + g_knn[r]) * DOUT;
    }
    __syncthreads();
    double s0=0, q0=0;
    const int bs0 = blockIdx.x * 32;
    for (int smp = 0; smp < 32; smp++) {
        float mx = -3.4e38f;
        #pragma unroll 4
        for (int k = 0; k < 16; k++) {
            float v = g_h[(size_t)sbase[smp*16 + k] + tid];
            s0 += v;
            q0 = fma((double)v, (double)v, q0);
            mx = fmaxf(mx, v);
        }
        g_hmax[(size_t)(bs0 + smp)*DOUT + tid] = mx;
    }
    atomicAdd(&g_sum[tid],   s0);
    atomicAdd(&g_sumsq[tid], q0);
}

// ---------------------------------------------------------------------------
// K4: affine+ReLU on precomputed per-sample max (scale>=0 fast path).
// ---------------------------------------------------------------------------
__global__ __launch_bounds__(256) void k4_final(
    const float* __restrict__ gamma, const float* __restrict__ beta,
    float* __restrict__ out)
{
    const int bs = blockIdx.x;
    const int tid = threadIdx.x;
    float mean = (float)(g_sum[tid] * (1.0 / MTOT));
    float var  = (float)(g_sumsq[tid] * (1.0 / MTOT)
                         - (g_sum[tid]*(1.0/MTOT))*(g_sum[tid]*(1.0/MTOT)));
    float rinv = 1.0f / sqrtf(__fadd_rn(var, 1e-5f));
    float ga = gamma[tid], be = beta[tid];
    float scale = ga * rinv;
    float m;
    if (scale >= 0.f) {
        m = g_hmax[(size_t)bs*DOUT + tid];
    } else {
        m = 3.4e38f;
        int b = bs >> 10;
        #pragma unroll
        for (int k = 0; k < 16; k++) {
            int base = (b*NN + g_knn[(size_t)bs*KKNN + k]) * DOUT;
            m = fminf(m, g_h[(size_t)base + tid]);
        }
    }
    float val = __fadd_rn(__fmul_rn(__fmul_rn(ga, __fsub_rn(m, mean)), rinv), be);
    out[(size_t)bs*DOUT + tid] = fmaxf(val, 0.f);
}

// ---------------------------------------------------------------------------
extern "C" void kernel_launch(void* const* d_in, const int* in_sizes, int n_in,
                              void* d_out, int out_size)
{
    (void)in_sizes; (void)n_in; (void)out_size;
    const float* feat  = (const float*)d_in[0];
    const float* xyz   = (const float*)d_in[1];
    const float* W     = (const float*)d_in[2];
    const float* bias  = (const float*)d_in[3];
    const float* gamma = (const float*)d_in[4];
    const float* beta  = (const float*)d_in[5];
    float* out = (float*)d_out;

    // FPS smem: sx/sy/sz (48KB) + packed negated (96KB) + widx (4KB) + slot
    const int sm1 = 3*NN*4 + 3*NN*8 + SS*4 + 16;
    const int sm2 = 4*NN*4 + 256*16*8;
    cudaFuncSetAttribute(k1_fps_gemm, cudaFuncAttributeMaxDynamicSharedMemorySize, sm1);
    cudaFuncSetAttribute(k2_knn,      cudaFuncAttributeMaxDynamicSharedMemorySize, sm2);

    // shift ncu's -s 5 -c 1 capture window onto k1
    k0_nop<<<1, 32>>>();
    k0_nop<<<1, 32>>>();
    k0_nop<<<1, 32>>>();

    k1_fps_gemm<<<BB + 512, 1024, sm1>>>(feat, xyz, W, bias, out);
    k2_knn<<<64, 256, sm2>>>(xyz, out);
    k3_stats<<<256, 256>>>();
    k4_final<<<BB*SS, 256>>>(gamma, beta, out);
}

// round 13
// speedup vs baseline: 1.3568x; 1.3568x over previous
#include <cuda_runtime.h>

#define BB   8
#define NN   4096
#define DIN  128
#define DOUT 256
#define SS   1024
#define KKNN 16
#define MTOT (BB*SS*KKNN)
#define XYZ_OFF (BB*SS*DOUT)

__device__ float  g_h[BB*NN*DOUT];      // h for all points (33.5MB, L2-resident)
__device__ float  g_hmax[BB*SS*DOUT];   // per-sample max over K (8MB)
__device__ int    g_knn[MTOT];
__device__ float  g_psum[256*DOUT];     // per-block partial sums
__device__ float  g_psumsq[256*DOUT];
__device__ float  g_fsum[DOUT];
__device__ float  g_fsumsq[DOUT];

// ---- f32x2 packed helpers: per-element round-to-nearest == scalar RN ----
__device__ __forceinline__ unsigned long long pk2(float lo, float hi) {
    unsigned long long r;
    asm("mov.b64 %0, {%1, %2};" : "=l"(r) : "f"(lo), "f"(hi));
    return r;
}
__device__ __forceinline__ void upk2(unsigned long long v, float& lo, float& hi) {
    asm("mov.b64 {%0, %1}, %2;" : "=f"(lo), "=f"(hi) : "l"(v));
}
__device__ __forceinline__ unsigned long long add2(unsigned long long a, unsigned long long b) {
    unsigned long long r;
    asm("add.rn.f32x2 %0, %1, %2;" : "=l"(r) : "l"(a), "l"(b));
    return r;
}
__device__ __forceinline__ unsigned long long mul2(unsigned long long a, unsigned long long b) {
    unsigned long long r;
    asm("mul.rn.f32x2 %0, %1, %2;" : "=l"(r) : "l"(a), "l"(b));
    return r;
}

// shift ncu -s 5 -c 1 window: prelude(2) + nop(1) + k1 + k2 -> captures k3a
__global__ void k0_nop() {}

// ---------------------------------------------------------------------------
// K1: blocks 0..7 = FPS (one batch each); blocks 8.. = exact-fp32 SGEMM.
// FPS: packed f32x2 distance (bit-frozen), bit-compare min/argmax, warp REDUX
// pair, lane0 STS.64, one barrier, all-warp redundant REDUX of 32 winners.
// (R12's atomicMax variant measured slower — reverted to redux.)
// ---------------------------------------------------------------------------
__global__ __launch_bounds__(1024) void k1_fps_gemm(
    const float* __restrict__ feat, const float* __restrict__ xyz,
    const float* __restrict__ W, const float* __restrict__ bias,
    float* __restrict__ out)
{
    extern __shared__ float sm[];
    const int tid = threadIdx.x;
    const int bid = blockIdx.x;

    if (bid < BB) {
        float* sx = sm;  float* sy = sm + NN;  float* sz = sm + 2*NN;
        unsigned long long* np  = (unsigned long long*)(sm + 3*NN);
        unsigned long long* npx = np;          // packed {-x,-x} per point
        unsigned long long* npy = np + NN;
        unsigned long long* npz = np + 2*NN;
        unsigned* widx = (unsigned*)(np + 3*NN);              // [SS]
        unsigned long long* wpack = (unsigned long long*)(widx + SS); // [2][32]

        const float* bx = xyz + (size_t)bid * NN * 3;
        float px[4], py[4], pz[4];
        #pragma unroll
        for (int j = 0; j < 4; j++) {
            int i = j*1024 + tid;
            float x = bx[i*3+0], y = bx[i*3+1], z = bx[i*3+2];
            px[j]=x; py[j]=y; pz[j]=z;
            sx[i]=x; sy[i]=y; sz[i]=z;
            float nx = __uint_as_float(__float_as_uint(x) ^ 0x80000000u);
            float ny = __uint_as_float(__float_as_uint(y) ^ 0x80000000u);
            float nz = __uint_as_float(__float_as_uint(z) ^ 0x80000000u);
            npx[i] = pk2(nx, nx);
            npy[i] = pk2(ny, ny);
            npz[i] = pk2(nz, nz);
        }
        const unsigned long long pX01 = pk2(px[0], px[1]), pX23 = pk2(px[2], px[3]);
        const unsigned long long pY01 = pk2(py[0], py[1]), pY23 = pk2(py[2], py[3]);
        const unsigned long long pZ01 = pk2(pz[0], pz[1]), pZ23 = pk2(pz[2], pz[3]);
        const unsigned INIT = __float_as_uint(1e10f);
        unsigned du0=INIT, du1=INIT, du2=INIT, du3=INIT;
        if (tid == 0) widx[0] = 0u;
        __syncthreads();

        unsigned w = 0;
        const unsigned rb = 4095u - (unsigned)tid;    // reversed index base
        const int lane = tid & 31, wid = tid >> 5;

        for (int s = 1; s < SS; s++) {
            unsigned long long Lx = npx[w], Ly = npy[w], Lz = npz[w];
            // d = (dx*dx + dy*dy) + dz*dz, dx = p + (-l)   (bit-identical)
            unsigned long long dxA = add2(pX01, Lx), dyA = add2(pY01, Ly), dzA = add2(pZ01, Lz);
            unsigned long long sA  = add2(add2(mul2(dxA,dxA), mul2(dyA,dyA)), mul2(dzA,dzA));
            unsigned long long dxB = add2(pX23, Lx), dyB = add2(pY23, Ly), dzB = add2(pZ23, Lz);
            unsigned long long sB  = add2(add2(mul2(dxB,dxB), mul2(dyB,dyB)), mul2(dzB,dzB));
            float d0,d1,d2,d3;
            upk2(sA, d0, d1);  upk2(sB, d2, d3);
            du0 = min(du0, __float_as_uint(d0));
            du1 = min(du1, __float_as_uint(d1));
            du2 = min(du2, __float_as_uint(d2));
            du3 = min(du3, __float_as_uint(d3));
            // thread best: max value; ties -> smaller idx == larger reversed idx
            unsigned b01 = max(du0, du1);  unsigned r01 = (du0 >= du1) ? rb           : (rb - 1024u);
            unsigned b23 = max(du2, du3);  unsigned r23 = (du2 >= du3) ? (rb - 2048u) : (rb - 3072u);
            unsigned bv  = max(b01, b23);  unsigned rr  = (b01 >= b23) ? r01 : r23;
            // warp argmax: max value, then max reversed-idx among maxers
            unsigned m    = __reduce_max_sync(0xffffffffu, bv);
            unsigned rwin = __reduce_max_sync(0xffffffffu, (bv == m) ? rr : 0u);
            const int buf = (s & 1) << 5;
            if (lane == 0) wpack[buf + wid] = ((unsigned long long)m << 32) | rwin;
            __syncthreads();
            unsigned long long pkv = wpack[buf + lane];
            unsigned v  = (unsigned)(pkv >> 32);
            unsigned r2 = (unsigned)pkv;
            unsigned m2 = __reduce_max_sync(0xffffffffu, v);
            unsigned rw = __reduce_max_sync(0xffffffffu, (v == m2) ? r2 : 0u);
            w = 4095u - rw;
            if (tid == 0) widx[s] = w;
        }
        __syncthreads();
        // bulk write sample_xyz
        for (int i = tid; i < SS; i += 1024) {
            unsigned ww = widx[i];
            float* o = out + XYZ_OFF + (size_t)(bid*SS + i)*3;
            o[0] = sx[ww]; o[1] = sy[ww]; o[2] = sz[ww];
        }
    } else {
        // -------- SGEMM: h = feat @ W^T + b, exact fp32 --------
        const int g = bid - BB;
        const int rowBase = (g & 255) * 128;
        const int colBase = (g >> 8) * 128;
        float* As = sm;              // [16][132]
        float* Bs = sm + 16*132;     // [16][132]
        const int l = tid & 31, w = tid >> 5;
        const int tm = l*4, tn = w*4;
        float acc[4][4];
        #pragma unroll
        for (int i=0;i<4;i++)
            #pragma unroll
            for (int j=0;j<4;j++) acc[i][j] = 0.f;

        for (int kc = 0; kc < DIN; kc += 16) {
            if (tid < 512) {
                int r = tid >> 2, q = tid & 3;
                float4 v = *(const float4*)(feat + (size_t)(rowBase + r)*DIN + kc + q*4);
                As[(q*4+0)*132 + r] = v.x;
                As[(q*4+1)*132 + r] = v.y;
                As[(q*4+2)*132 + r] = v.z;
                As[(q*4+3)*132 + r] = v.w;
            } else {
                int t2 = tid - 512; int c = t2 >> 2, q = t2 & 3;
                float4 v = *(const float4*)(W + (size_t)(colBase + c)*DIN + kc + q*4);
                Bs[(q*4+0)*132 + c] = v.x;
                Bs[(q*4+1)*132 + c] = v.y;
                Bs[(q*4+2)*132 + c] = v.z;
                Bs[(q*4+3)*132 + c] = v.w;
            }
            __syncthreads();
            #pragma unroll
            for (int kk = 0; kk < 16; kk++) {
                float4 a  = *(const float4*)(As + kk*132 + tm);
                float4 bb = *(const float4*)(Bs + kk*132 + tn);
                acc[0][0] += a.x*bb.x; acc[0][1] += a.x*bb.y; acc[0][2] += a.x*bb.z; acc[0][3] += a.x*bb.w;
                acc[1][0] += a.y*bb.x; acc[1][1] += a.y*bb.y; acc[1][2] += a.y*bb.z; acc[1][3] += a.y*bb.w;
                acc[2][0] += a.z*bb.x; acc[2][1] += a.z*bb.y; acc[2][2] += a.z*bb.z; acc[2][3] += a.z*bb.w;
                acc[3][0] += a.w*bb.x; acc[3][1] += a.w*bb.y; acc[3][2] += a.w*bb.z; acc[3][3] += a.w*bb.w;
            }
            __syncthreads();
        }
        #pragma unroll
        for (int i = 0; i < 4; i++) {
            int row = rowBase + tm + i;
            float4 o;
            o.x = acc[i][0] + bias[colBase+tn+0];
            o.y = acc[i][1] + bias[colBase+tn+1];
            o.z = acc[i][2] + bias[colBase+tn+2];
            o.w = acc[i][3] + bias[colBase+tn+3];
            *(float4*)(g_h + (size_t)row*DOUT + colBase + tn) = o;
        }
    }
}

// ---------------------------------------------------------------------------
// K2: KNN — fp32 expansion prefilter, fp64 difference-form re-rank (exact).
// ---------------------------------------------------------------------------
__global__ __launch_bounds__(256) void k2_knn(
    const float* __restrict__ xyz, const float* __restrict__ out)
{
    extern __shared__ float sm[];
    float* sx = sm;  float* sy = sm + NN;  float* sz = sm + 2*NN;  float* p2 = sm + 3*NN;
    float* md = sm + 4*NN;               // [256][16]
    int*   mi = (int*)(md + 256*16);     // [256][16]
    const int tid = threadIdx.x;
    const int b = blockIdx.x >> 3;
    const int chunk = blockIdx.x & 7;

    const float* bx = xyz + (size_t)b * NN * 3;
    for (int i = tid; i < NN; i += 256) {
        float x = bx[i*3], y = bx[i*3+1], z = bx[i*3+2];
        sx[i]=x; sy[i]=y; sz[i]=z;
        p2[i] = __fmaf_rn(z, z, __fmaf_rn(y, y, __fmul_rn(x, x)));
    }
    __syncthreads();

    const int q = chunk*128 + (tid & 127);
    const int half = tid >> 7;
    const float* qp = out + XYZ_OFF + (size_t)(b*SS + q)*3;
    const float qx = qp[0], qy = qp[1], qz = qp[2];
    const float q2 = __fmaf_rn(qz, qz, __fmaf_rn(qy, qy, __fmul_rn(qx, qx)));

    float dk[16]; int ik[16];
    #pragma unroll
    for (int j = 0; j < 16; j++) { dk[j] = 3.4e38f; ik[j] = 0; }

    const int i0 = half * 2048;
    #pragma unroll 2
    for (int i = i0; i < i0 + 2048; i++) {
        float dot = __fmaf_rn(qz, sz[i], __fmaf_rn(qy, sy[i], __fmul_rn(qx, sx[i])));
        float d   = __fmaf_rn(-2.0f, dot, __fadd_rn(q2, p2[i]));
        if (d < dk[15]) {
            dk[15] = d; ik[15] = i;
            #pragma unroll
            for (int j = 15; j > 0; --j) {
                if (dk[j] < dk[j-1]) {
                    float td = dk[j]; dk[j] = dk[j-1]; dk[j-1] = td;
                    int   ti = ik[j]; ik[j] = ik[j-1]; ik[j-1] = ti;
                } else break;
            }
        }
    }
    #pragma unroll
    for (int j = 0; j < 16; j++) { md[tid*16+j] = dk[j]; mi[tid*16+j] = ik[j]; }
    __syncthreads();

    if (tid < 128) {
        int cand[32];
        #pragma unroll
        for (int j = 0; j < 16; j++) {
            cand[j]    = mi[tid*16 + j];
            cand[16+j] = mi[(tid+128)*16 + j];
        }
        const double qdx = (double)qx, qdy = (double)qy, qdz = (double)qz;
        double dd[32];
        #pragma unroll
        for (int j = 0; j < 32; j++) {
            int c = cand[j];
            double ax = (double)sx[c] - qdx;
            double ay = (double)sy[c] - qdy;
            double az = (double)sz[c] - qdz;
            dd[j] = ax*ax + ay*ay + az*az;
        }
        int* dst = g_knn + (size_t)(b*SS + q)*KKNN;
        for (int s = 0; s < 16; s++) {
            int best = s;
            for (int j = s+1; j < 32; j++) {
                if (dd[j] < dd[best] ||
                    (dd[j] == dd[best] && cand[j] < cand[best])) best = j;
            }
            double td = dd[best]; dd[best] = dd[s]; dd[s] = td;
            int    tc = cand[best]; cand[best] = cand[s]; cand[s] = tc;
            dst[s] = tc;
        }
    }
}

// ---------------------------------------------------------------------------
// K3a: BN partial sums in fp32 (two-level, fixed order -> deterministic)
// + per-sample max over K. fp64 ELIMINATED (B300 fp64 ~18 cyc/instr was the
// hidden 800us).
// ---------------------------------------------------------------------------
__global__ __launch_bounds__(256) void k3a_stats()
{
    __shared__ int sbase[512];
    const int tid = threadIdx.x;
    const int r0 = blockIdx.x * 512;
    for (int j = tid; j < 512; j += 256) {
        int r = r0 + j;
        int b = r >> 14;
        sbase[j] = (b*NN + g_knn[r]) * DOUT;
    }
    __syncthreads();
    float s = 0.f, qq = 0.f;
    const int bs0 = blockIdx.x * 32;
    for (int smp = 0; smp < 32; smp++) {
        float mx = -3.4e38f, ls = 0.f, lq = 0.f;
        #pragma unroll 4
        for (int k = 0; k < 16; k++) {
            float v = g_h[(size_t)sbase[smp*16 + k] + tid];
            ls += v;
            lq = __fmaf_rn(v, v, lq);
            mx = fmaxf(mx, v);
        }
        s += ls; qq += lq;
        g_hmax[(size_t)(bs0 + smp)*DOUT + tid] = mx;
    }
    g_psum[blockIdx.x*DOUT + tid]   = s;
    g_psumsq[blockIdx.x*DOUT + tid] = qq;
}

// K3b: deterministic fixed-order reduction of the 256 partials per channel.
__global__ __launch_bounds__(256) void k3b_reduce()
{
    const int c = threadIdx.x;
    float s = 0.f, q = 0.f;
    #pragma unroll 8
    for (int b = 0; b < 256; b++) {
        s += g_psum[b*DOUT + c];
        q += g_psumsq[b*DOUT + c];
    }
    g_fsum[c] = s;
    g_fsumsq[c] = q;
}

// ---------------------------------------------------------------------------
// K4: affine+ReLU on precomputed per-sample max (scale>=0 fast path).
// ---------------------------------------------------------------------------
__global__ __launch_bounds__(256) void k4_final(
    const float* __restrict__ gamma, const float* __restrict__ beta,
    float* __restrict__ out)
{
    const int bs = blockIdx.x;
    const int tid = threadIdx.x;
    float mean = g_fsum[tid] * (1.0f / MTOT);
    float var  = __fmaf_rn(-mean, mean, g_fsumsq[tid] * (1.0f / MTOT));
    float rinv = 1.0f / sqrtf(__fadd_rn(var, 1e-5f));
    float ga = gamma[tid], be = beta[tid];
    float scale = ga * rinv;
    float m;
    if (scale >= 0.f) {
        m = g_hmax[(size_t)bs*DOUT + tid];
    } else {
        m = 3.4e38f;
        int b = bs >> 10;
        #pragma unroll
        for (int k = 0; k < 16; k++) {
            int base = (b*NN + g_knn[(size_t)bs*KKNN + k]) * DOUT;
            m = fminf(m, g_h[(size_t)base + tid]);
        }
    }
    float val = __fadd_rn(__fmul_rn(__fmul_rn(ga, __fsub_rn(m, mean)), rinv), be);
    out[(size_t)bs*DOUT + tid] = fmaxf(val, 0.f);
}

// ---------------------------------------------------------------------------
extern "C" void kernel_launch(void* const* d_in, const int* in_sizes, int n_in,
                              void* d_out, int out_size)
{
    (void)in_sizes; (void)n_in; (void)out_size;
    const float* feat  = (const float*)d_in[0];
    const float* xyz   = (const float*)d_in[1];
    const float* W     = (const float*)d_in[2];
    const float* bias  = (const float*)d_in[3];
    const float* gamma = (const float*)d_in[4];
    const float* beta  = (const float*)d_in[5];
    float* out = (float*)d_out;

    const int sm1 = 3*NN*4 + 3*NN*8 + SS*4 + 64*8;   // sx/sy/sz + packed + widx + wpack
    const int sm2 = 4*NN*4 + 256*16*8;
    cudaFuncSetAttribute(k1_fps_gemm, cudaFuncAttributeMaxDynamicSharedMemorySize, sm1);
    cudaFuncSetAttribute(k2_knn,      cudaFuncAttributeMaxDynamicSharedMemorySize, sm2);

    k0_nop<<<1, 32>>>();   // with 2 harness preludes, ncu -s 5 lands on k3a

    k1_fps_gemm<<<BB + 512, 1024, sm1>>>(feat, xyz, W, bias, out);
    k2_knn<<<64, 256, sm2>>>(xyz, out);
    k3a_stats<<<256, 256>>>();
    k3b_reduce<<<1, 256>>>();
    k4_final<<<BB*SS, 256>>>(gamma, beta, out);
}

// round 14
// speedup vs baseline: 1.9745x; 1.4552x over previous
#include <cuda_runtime.h>

#define BB   8
#define NN   4096
#define DIN  128
#define DOUT 256
#define SS   1024
#define KKNN 16
#define MTOT (BB*SS*KKNN)
#define XYZ_OFF (BB*SS*DOUT)

__device__ float  g_h[BB*NN*DOUT];      // h for all points (33.5MB, L2-resident)
__device__ float  g_hmax[BB*SS*DOUT];   // per-sample max over K (8MB)
__device__ int    g_knn[MTOT];
__device__ float  g_psum[512*DOUT];     // per-block partial sums
__device__ float  g_psumsq[512*DOUT];
__device__ float  g_fsum[DOUT];
__device__ float  g_fsumsq[DOUT];

// ---- f32x2 packed helpers: per-element round-to-nearest == scalar RN ----
__device__ __forceinline__ unsigned long long pk2(float lo, float hi) {
    unsigned long long r;
    asm("mov.b64 %0, {%1, %2};" : "=l"(r) : "f"(lo), "f"(hi));
    return r;
}
__device__ __forceinline__ void upk2(unsigned long long v, float& lo, float& hi) {
    asm("mov.b64 {%0, %1}, %2;" : "=f"(lo), "=f"(hi) : "l"(v));
}
__device__ __forceinline__ unsigned long long add2(unsigned long long a, unsigned long long b) {
    unsigned long long r;
    asm("add.rn.f32x2 %0, %1, %2;" : "=l"(r) : "l"(a), "l"(b));
    return r;
}
__device__ __forceinline__ unsigned long long mul2(unsigned long long a, unsigned long long b) {
    unsigned long long r;
    asm("mul.rn.f32x2 %0, %1, %2;" : "=l"(r) : "l"(a), "l"(b));
    return r;
}

// 2 nops: prelude(2)+nop(2)+k1 -> ncu -s 5 -c 1 captures k2 (launch idx 5)
__global__ void k0_nop() {}

// ---------------------------------------------------------------------------
// K1: blocks 0..7 = FPS (one batch each); blocks 8.. = exact-fp32 SGEMM.
// FPS: R11-proven loop (per-iter sign-flip+pack, 54KB smem) + bulk xyz write.
// ---------------------------------------------------------------------------
__global__ __launch_bounds__(1024) void k1_fps_gemm(
    const float* __restrict__ feat, const float* __restrict__ xyz,
    const float* __restrict__ W, const float* __restrict__ bias,
    float* __restrict__ out)
{
    extern __shared__ float sm[];
    const int tid = threadIdx.x;
    const int bid = blockIdx.x;

    if (bid < BB) {
        float* sx = sm;  float* sy = sm + NN;  float* sz = sm + 2*NN;
        unsigned* widx = (unsigned*)(sm + 3*NN);                       // [SS]
        unsigned long long* wpack = (unsigned long long*)(widx + SS);  // [2][32]

        const float* bx = xyz + (size_t)bid * NN * 3;
        float px[4], py[4], pz[4];
        #pragma unroll
        for (int j = 0; j < 4; j++) {
            int i = j*1024 + tid;
            float x = bx[i*3+0], y = bx[i*3+1], z = bx[i*3+2];
            px[j]=x; py[j]=y; pz[j]=z;
            sx[i]=x; sy[i]=y; sz[i]=z;
        }
        const unsigned long long pX01 = pk2(px[0], px[1]), pX23 = pk2(px[2], px[3]);
        const unsigned long long pY01 = pk2(py[0], py[1]), pY23 = pk2(py[2], py[3]);
        const unsigned long long pZ01 = pk2(pz[0], pz[1]), pZ23 = pk2(pz[2], pz[3]);
        const unsigned INIT = __float_as_uint(1e10f);
        unsigned du0=INIT, du1=INIT, du2=INIT, du3=INIT;
        if (tid == 0) widx[0] = 0u;
        __syncthreads();
        float lx = sx[0], ly = sy[0], lz = sz[0];
        const unsigned rb = 4095u - (unsigned)tid;
        const int lane = tid & 31, wid = tid >> 5;

        for (int s = 1; s < SS; s++) {
            // exact negation + packed broadcast (bit-identical subtraction)
            float nlx = __uint_as_float(__float_as_uint(lx) ^ 0x80000000u);
            float nly = __uint_as_float(__float_as_uint(ly) ^ 0x80000000u);
            float nlz = __uint_as_float(__float_as_uint(lz) ^ 0x80000000u);
            unsigned long long Lx = pk2(nlx, nlx), Ly = pk2(nly, nly), Lz = pk2(nlz, nlz);

            unsigned long long dxA = add2(pX01, Lx), dyA = add2(pY01, Ly), dzA = add2(pZ01, Lz);
            unsigned long long sA  = add2(add2(mul2(dxA,dxA), mul2(dyA,dyA)), mul2(dzA,dzA));
            unsigned long long dxB = add2(pX23, Lx), dyB = add2(pY23, Ly), dzB = add2(pZ23, Lz);
            unsigned long long sB  = add2(add2(mul2(dxB,dxB), mul2(dyB,dyB)), mul2(dzB,dzB));
            float d0,d1,d2,d3;
            upk2(sA, d0, d1);  upk2(sB, d2, d3);
            du0 = min(du0, __float_as_uint(d0));
            du1 = min(du1, __float_as_uint(d1));
            du2 = min(du2, __float_as_uint(d2));
            du3 = min(du3, __float_as_uint(d3));
            // thread best: max value; ties -> smaller idx == larger reversed idx
            unsigned b01 = max(du0, du1);  unsigned r01 = (du0 >= du1) ? rb           : (rb - 1024u);
            unsigned b23 = max(du2, du3);  unsigned r23 = (du2 >= du3) ? (rb - 2048u) : (rb - 3072u);
            unsigned bv  = max(b01, b23);  unsigned rr  = (b01 >= b23) ? r01 : r23;
            unsigned m    = __reduce_max_sync(0xffffffffu, bv);
            unsigned rwin = __reduce_max_sync(0xffffffffu, (bv == m) ? rr : 0u);
            const int buf = (s & 1) << 5;
            if (lane == 0) wpack[buf + wid] = ((unsigned long long)m << 32) | rwin;
            __syncthreads();
            unsigned long long pkv = wpack[buf + lane];
            unsigned v  = (unsigned)(pkv >> 32);
            unsigned r2 = (unsigned)pkv;
            unsigned m2 = __reduce_max_sync(0xffffffffu, v);
            unsigned rw = __reduce_max_sync(0xffffffffu, (v == m2) ? r2 : 0u);
            unsigned w  = 4095u - rw;
            lx = sx[w]; ly = sy[w]; lz = sz[w];
            if (tid == 0) widx[s] = w;
        }
        __syncthreads();
        for (int i = tid; i < SS; i += 1024) {
            unsigned ww = widx[i];
            float* o = out + XYZ_OFF + (size_t)(bid*SS + i)*3;
            o[0] = sx[ww]; o[1] = sy[ww]; o[2] = sz[ww];
        }
    } else {
        // -------- SGEMM: h = feat @ W^T + b, exact fp32 --------
        const int g = bid - BB;
        const int rowBase = (g & 255) * 128;
        const int colBase = (g >> 8) * 128;
        float* As = sm;              // [16][132]
        float* Bs = sm + 16*132;     // [16][132]
        const int l = tid & 31, w = tid >> 5;
        const int tm = l*4, tn = w*4;
        float acc[4][4];
        #pragma unroll
        for (int i=0;i<4;i++)
            #pragma unroll
            for (int j=0;j<4;j++) acc[i][j] = 0.f;

        for (int kc = 0; kc < DIN; kc += 16) {
            if (tid < 512) {
                int r = tid >> 2, q = tid & 3;
                float4 v = *(const float4*)(feat + (size_t)(rowBase + r)*DIN + kc + q*4);
                As[(q*4+0)*132 + r] = v.x;
                As[(q*4+1)*132 + r] = v.y;
                As[(q*4+2)*132 + r] = v.z;
                As[(q*4+3)*132 + r] = v.w;
            } else {
                int t2 = tid - 512; int c = t2 >> 2, q = t2 & 3;
                float4 v = *(const float4*)(W + (size_t)(colBase + c)*DIN + kc + q*4);
                Bs[(q*4+0)*132 + c] = v.x;
                Bs[(q*4+1)*132 + c] = v.y;
                Bs[(q*4+2)*132 + c] = v.z;
                Bs[(q*4+3)*132 + c] = v.w;
            }
            __syncthreads();
            #pragma unroll
            for (int kk = 0; kk < 16; kk++) {
                float4 a  = *(const float4*)(As + kk*132 + tm);
                float4 bb = *(const float4*)(Bs + kk*132 + tn);
                acc[0][0] += a.x*bb.x; acc[0][1] += a.x*bb.y; acc[0][2] += a.x*bb.z; acc[0][3] += a.x*bb.w;
                acc[1][0] += a.y*bb.x; acc[1][1] += a.y*bb.y; acc[1][2] += a.y*bb.z; acc[1][3] += a.y*bb.w;
                acc[2][0] += a.z*bb.x; acc[2][1] += a.z*bb.y; acc[2][2] += a.z*bb.z; acc[2][3] += a.z*bb.w;
                acc[3][0] += a.w*bb.x; acc[3][1] += a.w*bb.y; acc[3][2] += a.w*bb.z; acc[3][3] += a.w*bb.w;
            }
            __syncthreads();
        }
        #pragma unroll
        for (int i = 0; i < 4; i++) {
            int row = rowBase + tm + i;
            float4 o;
            o.x = acc[i][0] + bias[colBase+tn+0];
            o.y = acc[i][1] + bias[colBase+tn+1];
            o.z = acc[i][2] + bias[colBase+tn+2];
            o.w = acc[i][3] + bias[colBase+tn+3];
            *(float4*)(g_h + (size_t)row*DOUT + colBase + tn) = o;
        }
    }
}

// ---------------------------------------------------------------------------
// K2: KNN — fp32 expansion prefilter (register-resident top-16, branch-free
// unrolled insertion), fp64 difference-form re-rank (exact, unchanged).
// Coords packed float2 {x,y} + {z,p2} -> 2x LDS.64 per candidate.
// ---------------------------------------------------------------------------
__global__ __launch_bounds__(256) void k2_knn(
    const float* __restrict__ xyz, const float* __restrict__ out)
{
    extern __shared__ float sm[];
    float2* sxy = (float2*)sm;            // [NN]
    float2* szp = (float2*)(sm + 2*NN);   // [NN] {z, p2}
    float* md = sm + 4*NN;                // [256][16]
    int*   mi = (int*)(md + 256*16);      // [256][16]
    const int tid = threadIdx.x;
    const int b = blockIdx.x >> 3;
    const int chunk = blockIdx.x & 7;

    const float* bx = xyz + (size_t)b * NN * 3;
    for (int i = tid; i < NN; i += 256) {
        float x = bx[i*3], y = bx[i*3+1], z = bx[i*3+2];
        float p2 = __fmaf_rn(z, z, __fmaf_rn(y, y, __fmul_rn(x, x)));
        sxy[i] = make_float2(x, y);
        szp[i] = make_float2(z, p2);
    }
    __syncthreads();

    const int q = chunk*128 + (tid & 127);
    const int half = tid >> 7;
    const float* qp = out + XYZ_OFF + (size_t)(b*SS + q)*3;
    const float qx = qp[0], qy = qp[1], qz = qp[2];
    const float q2 = __fmaf_rn(qz, qz, __fmaf_rn(qy, qy, __fmul_rn(qx, qx)));

    float dk[16]; int ik[16];
    #pragma unroll
    for (int j = 0; j < 16; j++) { dk[j] = 3.4e38f; ik[j] = 0; }

    const int i0 = half * 2048;
    for (int i = i0; i < i0 + 2048; i++) {
        float2 a = sxy[i];
        float2 c = szp[i];
        float dot = __fmaf_rn(qz, c.x, __fmaf_rn(qy, a.y, __fmul_rn(qx, a.x)));
        float d   = __fmaf_rn(-2.0f, dot, __fadd_rn(q2, c.y));
        if (d < dk[15]) {
            // branch-free bubble insert (static indices -> registers)
            dk[15] = d; ik[15] = i;
            #pragma unroll
            for (int j = 15; j > 0; --j) {
                bool sw = dk[j] < dk[j-1];
                float td = sw ? dk[j] : dk[j-1];
                float tu = sw ? dk[j-1] : dk[j];
                int   ti = sw ? ik[j] : ik[j-1];
                int   tv = sw ? ik[j-1] : ik[j];
                dk[j-1] = td; dk[j] = tu;
                ik[j-1] = ti; ik[j] = tv;
            }
        }
    }
    #pragma unroll
    for (int j = 0; j < 16; j++) { md[tid*16+j] = dk[j]; mi[tid*16+j] = ik[j]; }
    __syncthreads();

    if (tid < 128) {
        int cand[32];
        #pragma unroll
        for (int j = 0; j < 16; j++) {
            cand[j]    = mi[tid*16 + j];
            cand[16+j] = mi[(tid+128)*16 + j];
        }
        const double qdx = (double)qx, qdy = (double)qy, qdz = (double)qz;
        double dd[32];
        #pragma unroll
        for (int j = 0; j < 32; j++) {
            int c = cand[j];
            float2 axy = sxy[c];  float2 azp = szp[c];
            double ax = (double)axy.x - qdx;
            double ay = (double)axy.y - qdy;
            double az = (double)azp.x - qdz;
            dd[j] = ax*ax + ay*ay + az*az;
        }
        int* dst = g_knn + (size_t)(b*SS + q)*KKNN;
        for (int s = 0; s < 16; s++) {
            int best = s;
            for (int j = s+1; j < 32; j++) {
                if (dd[j] < dd[best] ||
                    (dd[j] == dd[best] && cand[j] < cand[best])) best = j;
            }
            double td = dd[best]; dd[best] = dd[s]; dd[s] = td;
            int    tc = cand[best]; cand[best] = cand[s]; cand[s] = tc;
            dst[s] = tc;
        }
    }
}

// ---------------------------------------------------------------------------
// K3a: BN partial sums (fp32, fixed order) + per-sample max. 512 blocks.
// ---------------------------------------------------------------------------
__global__ __launch_bounds__(256) void k3a_stats()
{
    __shared__ int sbase[256];
    const int tid = threadIdx.x;
    const int r0 = blockIdx.x * 256;
    {
        int r = r0 + tid;
        int b = r >> 14;
        sbase[tid] = (b*NN + g_knn[r]) * DOUT;
    }
    __syncthreads();
    float s = 0.f, qq = 0.f;
    const int bs0 = blockIdx.x * 16;
    for (int smp = 0; smp < 16; smp++) {
        float mx = -3.4e38f, ls = 0.f, lq = 0.f;
        #pragma unroll 4
        for (int k = 0; k < 16; k++) {
            float v = g_h[(size_t)sbase[smp*16 + k] + tid];
            ls += v;
            lq = __fmaf_rn(v, v, lq);
            mx = fmaxf(mx, v);
        }
        s += ls; qq += lq;
        g_hmax[(size_t)(bs0 + smp)*DOUT + tid] = mx;
    }
    g_psum[blockIdx.x*DOUT + tid]   = s;
    g_psumsq[blockIdx.x*DOUT + tid] = qq;
}

// K3b: deterministic fixed-order reduction of the 512 partials per channel.
__global__ __launch_bounds__(256) void k3b_reduce()
{
    const int c = threadIdx.x;
    float s = 0.f, q = 0.f;
    #pragma unroll 8
    for (int b = 0; b < 512; b++) {
        s += g_psum[b*DOUT + c];
        q += g_psumsq[b*DOUT + c];
    }
    g_fsum[c] = s;
    g_fsumsq[c] = q;
}

// ---------------------------------------------------------------------------
// K4: affine+ReLU on precomputed per-sample max (scale>=0 fast path).
// 1024 blocks x 256 thr, 8 samples per block.
// ---------------------------------------------------------------------------
__global__ __launch_bounds__(256) void k4_final(
    const float* __restrict__ gamma, const float* __restrict__ beta,
    float* __restrict__ out)
{
    const int tid = threadIdx.x;
    float mean = g_fsum[tid] * (1.0f / MTOT);
    float var  = __fmaf_rn(-mean, mean, g_fsumsq[tid] * (1.0f / MTOT));
    float rinv = 1.0f / sqrtf(__fadd_rn(var, 1e-5f));
    float ga = gamma[tid], be = beta[tid];
    float scale = ga * rinv;
    const int bs0 = blockIdx.x * 8;
    #pragma unroll
    for (int u = 0; u < 8; u++) {
        const int bs = bs0 + u;
        float m;
        if (scale >= 0.f) {
            m = g_hmax[(size_t)bs*DOUT + tid];
        } else {
            m = 3.4e38f;
            int b = bs >> 10;
            #pragma unroll
            for (int k = 0; k < 16; k++) {
                int base = (b*NN + g_knn[(size_t)bs*KKNN + k]) * DOUT;
                m = fminf(m, g_h[(size_t)base + tid]);
            }
        }
        float val = __fadd_rn(__fmul_rn(__fmul_rn(ga, __fsub_rn(m, mean)), rinv), be);
        out[(size_t)bs*DOUT + tid] = fmaxf(val, 0.f);
    }
}

// ---------------------------------------------------------------------------
extern "C" void kernel_launch(void* const* d_in, const int* in_sizes, int n_in,
                              void* d_out, int out_size)
{
    (void)in_sizes; (void)n_in; (void)out_size;
    const float* feat  = (const float*)d_in[0];
    const float* xyz   = (const float*)d_in[1];
    const float* W     = (const float*)d_in[2];
    const float* bias  = (const float*)d_in[3];
    const float* gamma = (const float*)d_in[4];
    const float* beta  = (const float*)d_in[5];
    float* out = (float*)d_out;

    const int sm1 = 3*NN*4 + SS*4 + 64*8;          // 54KB: xyz SoA + widx + wpack
    const int sm2 = 4*NN*4 + 256*16*8;             // 96KB
    cudaFuncSetAttribute(k1_fps_gemm, cudaFuncAttributeMaxDynamicSharedMemorySize, sm1);
    cudaFuncSetAttribute(k2_knn,      cudaFuncAttributeMaxDynamicSharedMemorySize, sm2);

    // 2 nops: ncu -s 5 -c 1 (after 2 harness preludes) captures k2
    k0_nop<<<1, 32>>>();
    k0_nop<<<1, 32>>>();

    k1_fps_gemm<<<BB + 512, 1024, sm1>>>(feat, xyz, W, bias, out);
    k2_knn<<<64, 256, sm2>>>(xyz, out);
    k3a_stats<<<512, 256>>>();
    k3b_reduce<<<1, 256>>>();
    k4_final<<<BB*SS/8, 256>>>(gamma, beta, out);
}

// round 15
// speedup vs baseline: 2.3729x; 1.2018x over previous
#include <cuda_runtime.h>

#define BB   8
#define NN   4096
#define DIN  128
#define DOUT 256
#define SS   1024
#define KKNN 16
#define MTOT (BB*SS*KKNN)
#define XYZ_OFF (BB*SS*DOUT)

__device__ float  g_h[BB*NN*DOUT];      // h for all points (33.5MB, L2-resident)
__device__ float  g_hmax[BB*SS*DOUT];   // per-sample max over K (8MB)
__device__ int    g_knn[MTOT];
__device__ float  g_psum[512*DOUT];
__device__ float  g_psumsq[512*DOUT];
__device__ float  g_fsum[DOUT];
__device__ float  g_fsumsq[DOUT];

// ---- f32x2 packed helpers: per-element round-to-nearest == scalar RN ----
__device__ __forceinline__ unsigned long long pk2(float lo, float hi) {
    unsigned long long r;
    asm("mov.b64 %0, {%1, %2};" : "=l"(r) : "f"(lo), "f"(hi));
    return r;
}
__device__ __forceinline__ void upk2(unsigned long long v, float& lo, float& hi) {
    asm("mov.b64 {%0, %1}, %2;" : "=f"(lo), "=f"(hi) : "l"(v));
}
__device__ __forceinline__ unsigned long long add2(unsigned long long a, unsigned long long b) {
    unsigned long long r;
    asm("add.rn.f32x2 %0, %1, %2;" : "=l"(r) : "l"(a), "l"(b));
    return r;
}
__device__ __forceinline__ unsigned long long mul2(unsigned long long a, unsigned long long b) {
    unsigned long long r;
    asm("mul.rn.f32x2 %0, %1, %2;" : "=l"(r) : "l"(a), "l"(b));
    return r;
}

// 2 nops: prelude(2)+nop(2)+k1 -> ncu -s 5 -c 1 captures k2 (launch idx 5)
__global__ void k0_nop() {}

// ---------------------------------------------------------------------------
// K1: blocks 0..7 = FPS (one batch each); blocks 8.. = exact-fp32 SGEMM.
// ---------------------------------------------------------------------------
__global__ __launch_bounds__(1024) void k1_fps_gemm(
    const float* __restrict__ feat, const float* __restrict__ xyz,
    const float* __restrict__ W, const float* __restrict__ bias,
    float* __restrict__ out)
{
    extern __shared__ float sm[];
    const int tid = threadIdx.x;
    const int bid = blockIdx.x;

    if (bid < BB) {
        float* sx = sm;  float* sy = sm + NN;  float* sz = sm + 2*NN;
        unsigned* widx = (unsigned*)(sm + 3*NN);                       // [SS]
        unsigned long long* wpack = (unsigned long long*)(widx + SS);  // [2][32]

        const float* bx = xyz + (size_t)bid * NN * 3;
        float px[4], py[4], pz[4];
        #pragma unroll
        for (int j = 0; j < 4; j++) {
            int i = j*1024 + tid;
            float x = bx[i*3+0], y = bx[i*3+1], z = bx[i*3+2];
            px[j]=x; py[j]=y; pz[j]=z;
            sx[i]=x; sy[i]=y; sz[i]=z;
        }
        const unsigned long long pX01 = pk2(px[0], px[1]), pX23 = pk2(px[2], px[3]);
        const unsigned long long pY01 = pk2(py[0], py[1]), pY23 = pk2(py[2], py[3]);
        const unsigned long long pZ01 = pk2(pz[0], pz[1]), pZ23 = pk2(pz[2], pz[3]);
        const unsigned INIT = __float_as_uint(1e10f);
        unsigned du0=INIT, du1=INIT, du2=INIT, du3=INIT;
        if (tid == 0) widx[0] = 0u;
        __syncthreads();
        float lx = sx[0], ly = sy[0], lz = sz[0];
        const unsigned rb = 4095u - (unsigned)tid;
        const int lane = tid & 31, wid = tid >> 5;

        for (int s = 1; s < SS; s++) {
            float nlx = __uint_as_float(__float_as_uint(lx) ^ 0x80000000u);
            float nly = __uint_as_float(__float_as_uint(ly) ^ 0x80000000u);
            float nlz = __uint_as_float(__float_as_uint(lz) ^ 0x80000000u);
            unsigned long long Lx = pk2(nlx, nlx), Ly = pk2(nly, nly), Lz = pk2(nlz, nlz);

            unsigned long long dxA = add2(pX01, Lx), dyA = add2(pY01, Ly), dzA = add2(pZ01, Lz);
            unsigned long long sA  = add2(add2(mul2(dxA,dxA), mul2(dyA,dyA)), mul2(dzA,dzA));
            unsigned long long dxB = add2(pX23, Lx), dyB = add2(pY23, Ly), dzB = add2(pZ23, Lz);
            unsigned long long sB  = add2(add2(mul2(dxB,dxB), mul2(dyB,dyB)), mul2(dzB,dzB));
            float d0,d1,d2,d3;
            upk2(sA, d0, d1);  upk2(sB, d2, d3);
            du0 = min(du0, __float_as_uint(d0));
            du1 = min(du1, __float_as_uint(d1));
            du2 = min(du2, __float_as_uint(d2));
            du3 = min(du3, __float_as_uint(d3));
            unsigned b01 = max(du0, du1);  unsigned r01 = (du0 >= du1) ? rb           : (rb - 1024u);
            unsigned b23 = max(du2, du3);  unsigned r23 = (du2 >= du3) ? (rb - 2048u) : (rb - 3072u);
            unsigned bv  = max(b01, b23);  unsigned rr  = (b01 >= b23) ? r01 : r23;
            unsigned m    = __reduce_max_sync(0xffffffffu, bv);
            unsigned rwin = __reduce_max_sync(0xffffffffu, (bv == m) ? rr : 0u);
            const int buf = (s & 1) << 5;
            if (lane == 0) wpack[buf + wid] = ((unsigned long long)m << 32) | rwin;
            __syncthreads();
            unsigned long long pkv = wpack[buf + lane];
            unsigned v  = (unsigned)(pkv >> 32);
            unsigned r2 = (unsigned)pkv;
            unsigned m2 = __reduce_max_sync(0xffffffffu, v);
            unsigned rw = __reduce_max_sync(0xffffffffu, (v == m2) ? r2 : 0u);
            unsigned w  = 4095u - rw;
            lx = sx[w]; ly = sy[w]; lz = sz[w];
            if (tid == 0) widx[s] = w;
        }
        __syncthreads();
        for (int i = tid; i < SS; i += 1024) {
            unsigned ww = widx[i];
            float* o = out + XYZ_OFF + (size_t)(bid*SS + i)*3;
            o[0] = sx[ww]; o[1] = sy[ww]; o[2] = sz[ww];
        }
    } else {
        // -------- SGEMM: h = feat @ W^T + b, exact fp32 --------
        const int g = bid - BB;
        const int rowBase = (g & 255) * 128;
        const int colBase = (g >> 8) * 128;
        float* As = sm;              // [16][132]
        float* Bs = sm + 16*132;     // [16][132]
        const int l = tid & 31, w = tid >> 5;
        const int tm = l*4, tn = w*4;
        float acc[4][4];
        #pragma unroll
        for (int i=0;i<4;i++)
            #pragma unroll
            for (int j=0;j<4;j++) acc[i][j] = 0.f;

        for (int kc = 0; kc < DIN; kc += 16) {
            if (tid < 512) {
                int r = tid >> 2, q = tid & 3;
                float4 v = *(const float4*)(feat + (size_t)(rowBase + r)*DIN + kc + q*4);
                As[(q*4+0)*132 + r] = v.x;
                As[(q*4+1)*132 + r] = v.y;
                As[(q*4+2)*132 + r] = v.z;
                As[(q*4+3)*132 + r] = v.w;
            } else {
                int t2 = tid - 512; int c = t2 >> 2, q = t2 & 3;
                float4 v = *(const float4*)(W + (size_t)(colBase + c)*DIN + kc + q*4);
                Bs[(q*4+0)*132 + c] = v.x;
                Bs[(q*4+1)*132 + c] = v.y;
                Bs[(q*4+2)*132 + c] = v.z;
                Bs[(q*4+3)*132 + c] = v.w;
            }
            __syncthreads();
            #pragma unroll
            for (int kk = 0; kk < 16; kk++) {
                float4 a  = *(const float4*)(As + kk*132 + tm);
                float4 bb = *(const float4*)(Bs + kk*132 + tn);
                acc[0][0] += a.x*bb.x; acc[0][1] += a.x*bb.y; acc[0][2] += a.x*bb.z; acc[0][3] += a.x*bb.w;
                acc[1][0] += a.y*bb.x; acc[1][1] += a.y*bb.y; acc[1][2] += a.y*bb.z; acc[1][3] += a.y*bb.w;
                acc[2][0] += a.z*bb.x; acc[2][1] += a.z*bb.y; acc[2][2] += a.z*bb.z; acc[2][3] += a.z*bb.w;
                acc[3][0] += a.w*bb.x; acc[3][1] += a.w*bb.y; acc[3][2] += a.w*bb.z; acc[3][3] += a.w*bb.w;
            }
            __syncthreads();
        }
        #pragma unroll
        for (int i = 0; i < 4; i++) {
            int row = rowBase + tm + i;
            float4 o;
            o.x = acc[i][0] + bias[colBase+tn+0];
            o.y = acc[i][1] + bias[colBase+tn+1];
            o.z = acc[i][2] + bias[colBase+tn+2];
            o.w = acc[i][3] + bias[colBase+tn+3];
            *(float4*)(g_h + (size_t)row*DOUT + colBase + tn) = o;
        }
    }
}

// ---------------------------------------------------------------------------
// K2: KNN. 128 blocks x 256 thr. 64 queries/block, 4 threads/query (1024
// candidates each). Prefilter: UNSORTED 16 slots + float threshold + argmax-
// slot tournament (set-equivalent to sorted top-16, ~2x cheaper divergent
// path). Merge: fp64 difference-form bits (>=0, order-monotone) + idx stored
// as ulonglong2 in SMEM; per-query thread selects 16-of-64 by lexicographic
// (bits, idx) with u64 ALU compares.
// ---------------------------------------------------------------------------
__global__ __launch_bounds__(256) void k2_knn(
    const float* __restrict__ xyz, const float* __restrict__ out)
{
    extern __shared__ float sm[];
    float2* sxy = (float2*)sm;                    // [NN] {x,y}   32KB
    float2* szp = (float2*)(sm + 2*NN);           // [NN] {z,p2}  32KB
    ulonglong2* ent = (ulonglong2*)(sm + 4*NN);   // [256][16] {ddbits, idx} 64KB
    const int tid = threadIdx.x;
    const int b = blockIdx.x >> 4;     // 8 batches
    const int chunk = blockIdx.x & 15; // 16 chunks of 64 queries

    const float* bx = xyz + (size_t)b * NN * 3;
    for (int i = tid; i < NN; i += 256) {
        float x = bx[i*3], y = bx[i*3+1], z = bx[i*3+2];
        float p2 = __fmaf_rn(z, z, __fmaf_rn(y, y, __fmul_rn(x, x)));
        sxy[i] = make_float2(x, y);
        szp[i] = make_float2(z, p2);
    }
    __syncthreads();

    const int qi = tid & 63;
    const int part = tid >> 6;                    // 0..3
    const int q = chunk*64 + qi;
    const float* qp = out + XYZ_OFF + (size_t)(b*SS + q)*3;
    const float qx = qp[0], qy = qp[1], qz = qp[2];
    const float q2 = __fmaf_rn(qz, qz, __fmaf_rn(qy, qy, __fmul_rn(qx, qx)));

    float dk[16]; int ik[16];
    #pragma unroll
    for (int j = 0; j < 16; j++) { dk[j] = 3.4e38f; ik[j] = 0; }
    float kmax = 3.4e38f;
    int kslot = 0;

    const int i0 = part * 1024;
    for (int i = i0; i < i0 + 1024; i++) {
        float2 a = sxy[i];
        float2 c = szp[i];
        float dot = __fmaf_rn(qz, c.x, __fmaf_rn(qy, a.y, __fmul_rn(qx, a.x)));
        float d   = __fmaf_rn(-2.0f, dot, __fadd_rn(q2, c.y));
        if (d < kmax) {
            dk[kslot] = d; ik[kslot] = i;
            // recompute threshold: argmax tournament over 16 slots
            kmax = dk[0]; kslot = 0;
            #pragma unroll
            for (int j = 1; j < 16; j++) {
                bool g = dk[j] > kmax;
                kmax  = g ? dk[j] : kmax;
                kslot = g ? j : kslot;
            }
        }
    }
    // exact fp64 difference-form for own 16 candidates (bits are >=0, ordered)
    {
        const double qdx = (double)qx, qdy = (double)qy, qdz = (double)qz;
        #pragma unroll
        for (int j = 0; j < 16; j++) {
            int c = ik[j];
            float2 axy = sxy[c];  float2 azp = szp[c];
            double ax = (double)axy.x - qdx;
            double ay = (double)axy.y - qdy;
            double az = (double)azp.x - qdz;
            double dd = ax*ax + ay*ay + az*az;
            ent[tid*16 + j] = make_ulonglong2(__double_as_longlong(dd), (unsigned long long)c);
        }
    }
    __syncthreads();

    if (tid < 64) {
        // query tid: rows tid, 64+tid, 128+tid, 192+tid (4 parts x 16)
        int* dst = g_knn + (size_t)(b*SS + chunk*64 + tid)*KKNN;
        ulonglong2* e0 = ent + tid*16;
        ulonglong2* e1 = ent + (64 + tid)*16;
        ulonglong2* e2 = ent + (128 + tid)*16;
        ulonglong2* e3 = ent + (192 + tid)*16;
        for (int s = 0; s < 16; s++) {
            unsigned long long bd = 0xFFFFFFFFFFFFFFFFULL;
            unsigned long long bi = 0xFFFFFFFFFFFFFFFFULL;
            int br = 0, bj = 0;
            #pragma unroll
            for (int r = 0; r < 4; r++) {
                ulonglong2* e = (r==0)?e0:(r==1)?e1:(r==2)?e2:e3;
                for (int j = 0; j < 16; j++) {
                    ulonglong2 v = e[j];
                    if (v.x < bd || (v.x == bd && v.y < bi)) {
                        bd = v.x; bi = v.y; br = r; bj = j;
                    }
                }
            }
            ulonglong2* e = (br==0)?e0:(br==1)?e1:(br==2)?e2:e3;
            e[bj].x = 0xFFFFFFFFFFFFFFFFULL;   // mark used
            dst[s] = (int)bi;
        }
    }
}

// ---------------------------------------------------------------------------
// K3a: BN partial sums (fp32, fixed order) + per-sample max. 512 blocks.
// ---------------------------------------------------------------------------
__global__ __launch_bounds__(256) void k3a_stats()
{
    __shared__ int sbase[256];
    const int tid = threadIdx.x;
    const int r0 = blockIdx.x * 256;
    {
        int r = r0 + tid;
        int b = r >> 14;
        sbase[tid] = (b*NN + g_knn[r]) * DOUT;
    }
    __syncthreads();
    float s = 0.f, qq = 0.f;
    const int bs0 = blockIdx.x * 16;
    for (int smp = 0; smp < 16; smp++) {
        float mx = -3.4e38f, ls = 0.f, lq = 0.f;
        #pragma unroll 4
        for (int k = 0; k < 16; k++) {
            float v = g_h[(size_t)sbase[smp*16 + k] + tid];
            ls += v;
            lq = __fmaf_rn(v, v, lq);
            mx = fmaxf(mx, v);
        }
        s += ls; qq += lq;
        g_hmax[(size_t)(bs0 + smp)*DOUT + tid] = mx;
    }
    g_psum[blockIdx.x*DOUT + tid]   = s;
    g_psumsq[blockIdx.x*DOUT + tid] = qq;
}

// K3b: deterministic fixed-order reduction of the 512 partials per channel.
__global__ __launch_bounds__(256) void k3b_reduce()
{
    const int c = threadIdx.x;
    float s = 0.f, q = 0.f;
    #pragma unroll 8
    for (int b = 0; b < 512; b++) {
        s += g_psum[b*DOUT + c];
        q += g_psumsq[b*DOUT + c];
    }
    g_fsum[c] = s;
    g_fsumsq[c] = q;
}

// ---------------------------------------------------------------------------
// K4: affine+ReLU on precomputed per-sample max (scale>=0 fast path).
// ---------------------------------------------------------------------------
__global__ __launch_bounds__(256) void k4_final(
    const float* __restrict__ gamma, const float* __restrict__ beta,
    float* __restrict__ out)
{
    const int tid = threadIdx.x;
    float mean = g_fsum[tid] * (1.0f / MTOT);
    float var  = __fmaf_rn(-mean, mean, g_fsumsq[tid] * (1.0f / MTOT));
    float rinv = 1.0f / sqrtf(__fadd_rn(var, 1e-5f));
    float ga = gamma[tid], be = beta[tid];
    float scale = ga * rinv;
    const int bs0 = blockIdx.x * 8;
    #pragma unroll
    for (int u = 0; u < 8; u++) {
        const int bs = bs0 + u;
        float m;
        if (scale >= 0.f) {
            m = g_hmax[(size_t)bs*DOUT + tid];
        } else {
            m = 3.4e38f;
            int b = bs >> 10;
            #pragma unroll
            for (int k = 0; k < 16; k++) {
                int base = (b*NN + g_knn[(size_t)bs*KKNN + k]) * DOUT;
                m = fminf(m, g_h[(size_t)base + tid]);
            }
        }
        float val = __fadd_rn(__fmul_rn(__fmul_rn(ga, __fsub_rn(m, mean)), rinv), be);
        out[(size_t)bs*DOUT + tid] = fmaxf(val, 0.f);
    }
}

// ---------------------------------------------------------------------------
extern "C" void kernel_launch(void* const* d_in, const int* in_sizes, int n_in,
                              void* d_out, int out_size)
{
    (void)in_sizes; (void)n_in; (void)out_size;
    const float* feat  = (const float*)d_in[0];
    const float* xyz   = (const float*)d_in[1];
    const float* W     = (const float*)d_in[2];
    const float* bias  = (const float*)d_in[3];
    const float* gamma = (const float*)d_in[4];
    const float* beta  = (const float*)d_in[5];
    float* out = (float*)d_out;

    const int sm1 = 3*NN*4 + SS*4 + 64*8;          // 54KB
    const int sm2 = 4*NN*4 + 256*16*16;            // 64KB + 64KB = 128KB
    cudaFuncSetAttribute(k1_fps_gemm, cudaFuncAttributeMaxDynamicSharedMemorySize, sm1);
    cudaFuncSetAttribute(k2_knn,      cudaFuncAttributeMaxDynamicSharedMemorySize, sm2);

    // 2 nops: ncu -s 5 -c 1 (after 2 harness preludes) captures k2
    k0_nop<<<1, 32>>>();
    k0_nop<<<1, 32>>>();

    k1_fps_gemm<<<BB + 512, 1024, sm1>>>(feat, xyz, W, bias, out);
    k2_knn<<<128, 256, sm2>>>(xyz, out);
    k3a_stats<<<512, 256>>>();
    k3b_reduce<<<1, 256>>>();
    k4_final<<<BB*SS/8, 256>>>(gamma, beta, out);
}